// round 2
// baseline (speedup 1.0000x reference)
#include <cuda_runtime.h>
#include <math.h>

// Problem constants
constexpr int NB = 2;      // batch
constexpr int L  = 2048;   // seq len
constexpr int D  = 1024;   // embed dim
constexpr int H  = 16;     // heads
constexpr int HD = 64;     // head dim
constexpr float SM_SCALE = 0.03125f; // 1/sqrt(1024)

// Scratch (device globals: allocation-free rule)
__device__ float g_Q[NB * L * D];
__device__ float g_K[NB * L * D];
__device__ float g_V[NB * L * D];
__device__ float g_AO[NB * L * D];

// ---------------------------------------------------------------------------
// GEMM: C[M,N] = A[M,K] @ W[N,K]^T + bias[N]
// 128x128 block tile, BK=8, 256 threads, 8x8 per-thread micro-tile.
// ---------------------------------------------------------------------------
__global__ __launch_bounds__(256) void gemm_xWT_bias(
    const float* __restrict__ A, const float* __restrict__ W,
    const float* __restrict__ bias, float* __restrict__ C,
    int M, int N, int K)
{
    __shared__ float As[8][128];
    __shared__ float Bs[8][128];

    const int tid = threadIdx.x;
    const int tx = tid & 15;        // 0..15 -> n micro
    const int ty = tid >> 4;        // 0..15 -> m micro
    const int m0 = blockIdx.y * 128;
    const int n0 = blockIdx.x * 128;

    const int lrow = tid >> 1;          // 0..127
    const int lk4  = (tid & 1) * 4;     // 0 or 4
    const float* Aptr = A + (size_t)(m0 + lrow) * K + lk4;
    const float* Wptr = W + (size_t)(n0 + lrow) * K + lk4;

    float acc[8][8];
#pragma unroll
    for (int i = 0; i < 8; i++)
#pragma unroll
        for (int j = 0; j < 8; j++) acc[i][j] = 0.f;

    for (int k0 = 0; k0 < K; k0 += 8) {
        float4 av = *(const float4*)(Aptr + k0);
        float4 bv = *(const float4*)(Wptr + k0);
        As[lk4 + 0][lrow] = av.x; As[lk4 + 1][lrow] = av.y;
        As[lk4 + 2][lrow] = av.z; As[lk4 + 3][lrow] = av.w;
        Bs[lk4 + 0][lrow] = bv.x; Bs[lk4 + 1][lrow] = bv.y;
        Bs[lk4 + 2][lrow] = bv.z; Bs[lk4 + 3][lrow] = bv.w;
        __syncthreads();

#pragma unroll
        for (int kk = 0; kk < 8; kk++) {
            float a[8], b[8];
            *(float4*)&a[0] = *(const float4*)&As[kk][ty * 8];
            *(float4*)&a[4] = *(const float4*)&As[kk][ty * 8 + 4];
            *(float4*)&b[0] = *(const float4*)&Bs[kk][tx * 8];
            *(float4*)&b[4] = *(const float4*)&Bs[kk][tx * 8 + 4];
#pragma unroll
            for (int i = 0; i < 8; i++)
#pragma unroll
                for (int j = 0; j < 8; j++)
                    acc[i][j] += a[i] * b[j];
        }
        __syncthreads();
    }

    // Epilogue with bias
    float4 bia0 = *(const float4*)&bias[n0 + tx * 8];
    float4 bia1 = *(const float4*)&bias[n0 + tx * 8 + 4];
#pragma unroll
    for (int i = 0; i < 8; i++) {
        size_t row = (size_t)(m0 + ty * 8 + i);
        float* cp = C + row * N + n0 + tx * 8;
        float4 o0 = make_float4(acc[i][0] + bia0.x, acc[i][1] + bia0.y,
                                acc[i][2] + bia0.z, acc[i][3] + bia0.w);
        float4 o1 = make_float4(acc[i][4] + bia1.x, acc[i][5] + bia1.y,
                                acc[i][6] + bia1.z, acc[i][7] + bia1.w);
        *(float4*)cp = o0;
        *(float4*)(cp + 4) = o1;
    }
}

// ---------------------------------------------------------------------------
// Flash attention (fp32, online softmax).
// One block per (q-tile of 64, head, batch). 256 threads.
// K/V streamed in tiles of 32 rows. Hd = 64.
// ---------------------------------------------------------------------------
__global__ __launch_bounds__(256) void flash_attn(
    const float* __restrict__ Q, const float* __restrict__ K,
    const float* __restrict__ V, const int* __restrict__ mask,
    float* __restrict__ O)
{
    constexpr int BQ = 64, BK = 32;
    __shared__ float Qs[BQ][68];     // 68 keeps float4 rows 16B-aligned
    __shared__ float Ks[BK][68];
    __shared__ float Vs[BK][68];
    __shared__ float Ss[BQ][33];
    __shared__ float m_s[BQ], l_s[BQ], fac[BQ];

    const int tid = threadIdx.x;
    const int tx = tid & 15;     // 16
    const int ty = tid >> 4;     // 16
    const int qt = blockIdx.x;   // 0..31
    const int h  = blockIdx.y;   // 0..15
    const int n  = blockIdx.z;   // 0..1

    const float* Qb = Q + ((size_t)(n * L) + qt * BQ) * D + h * HD;
    for (int i = tid; i < BQ * 16; i += 256) {
        int r = i >> 4, c = (i & 15) * 4;
        float4 v = *(const float4*)(Qb + (size_t)r * D + c);
        Qs[r][c] = v.x; Qs[r][c + 1] = v.y; Qs[r][c + 2] = v.z; Qs[r][c + 3] = v.w;
    }
    if (tid < BQ) { m_s[tid] = -INFINITY; l_s[tid] = 0.f; }

    float acc[4][4];
#pragma unroll
    for (int i = 0; i < 4; i++)
#pragma unroll
        for (int j = 0; j < 4; j++) acc[i][j] = 0.f;
    __syncthreads();

    const int* mrow = mask + n * L;

    for (int kb = 0; kb < L / BK; ++kb) {
        const float* Kb = K + ((size_t)(n * L) + kb * BK) * D + h * HD;
        const float* Vb = V + ((size_t)(n * L) + kb * BK) * D + h * HD;
        for (int i = tid; i < BK * 16; i += 256) {
            int r = i >> 4, c = (i & 15) * 4;
            float4 kv = *(const float4*)(Kb + (size_t)r * D + c);
            Ks[r][c] = kv.x; Ks[r][c + 1] = kv.y; Ks[r][c + 2] = kv.z; Ks[r][c + 3] = kv.w;
            float4 vv = *(const float4*)(Vb + (size_t)r * D + c);
            Vs[r][c] = vv.x; Vs[r][c + 1] = vv.y; Vs[r][c + 2] = vv.z; Vs[r][c + 3] = vv.w;
        }
        __syncthreads();

        // S[ty*4+i][tx*2+j] = Q row . K row
        float s[4][2] = {{0.f, 0.f}, {0.f, 0.f}, {0.f, 0.f}, {0.f, 0.f}};
#pragma unroll
        for (int d0 = 0; d0 < HD; d0 += 4) {
            float a[4][4], b[2][4];
#pragma unroll
            for (int i = 0; i < 4; i++)
                *(float4*)a[i] = *(const float4*)&Qs[ty * 4 + i][d0];
#pragma unroll
            for (int j = 0; j < 2; j++)
                *(float4*)b[j] = *(const float4*)&Ks[tx * 2 + j][d0];
#pragma unroll
            for (int kk = 0; kk < 4; kk++)
#pragma unroll
                for (int i = 0; i < 4; i++)
#pragma unroll
                    for (int j = 0; j < 2; j++)
                        s[i][j] += a[i][kk] * b[j][kk];
        }

        // mask + scale, stage to smem
#pragma unroll
        for (int j = 0; j < 2; j++) {
            int kpos = kb * BK + tx * 2 + j;
            bool mz = (mrow[kpos] == 0);
#pragma unroll
            for (int i = 0; i < 4; i++)
                Ss[ty * 4 + i][tx * 2 + j] = (mz ? -1e20f : s[i][j]) * SM_SCALE;
        }
        __syncthreads();

        // Online softmax bookkeeping: one thread per query row
        if (tid < BQ) {
            float mold = m_s[tid];
            float mx = mold;
#pragma unroll
            for (int j = 0; j < BK; j++) mx = fmaxf(mx, Ss[tid][j]);
            float f = __expf(mold - mx);   // 0 when mold = -inf
            float sum = 0.f;
#pragma unroll
            for (int j = 0; j < BK; j++) {
                float p = __expf(Ss[tid][j] - mx);
                Ss[tid][j] = p;
                sum += p;
            }
            l_s[tid] = l_s[tid] * f + sum;
            m_s[tid] = mx;
            fac[tid] = f;
        }
        __syncthreads();

        // Rescale accumulators, then O += P @ V
#pragma unroll
        for (int i = 0; i < 4; i++) {
            float f = fac[ty * 4 + i];
            acc[i][0] *= f; acc[i][1] *= f; acc[i][2] *= f; acc[i][3] *= f;
        }
#pragma unroll 4
        for (int k = 0; k < BK; k++) {
            float4 bv = *(const float4*)&Vs[k][tx * 4];
#pragma unroll
            for (int i = 0; i < 4; i++) {
                float p = Ss[ty * 4 + i][k];
                acc[i][0] += p * bv.x; acc[i][1] += p * bv.y;
                acc[i][2] += p * bv.z; acc[i][3] += p * bv.w;
            }
        }
        __syncthreads();
    }

    float* Ob = O + ((size_t)(n * L) + qt * BQ) * D + h * HD;
#pragma unroll
    for (int i = 0; i < 4; i++) {
        int row = ty * 4 + i;
        float inv = 1.0f / l_s[row];
        float4 o = make_float4(acc[i][0] * inv, acc[i][1] * inv,
                               acc[i][2] * inv, acc[i][3] * inv);
        *(float4*)(Ob + (size_t)row * D + tx * 4) = o;
    }
}

// ---------------------------------------------------------------------------
// Launch
// ---------------------------------------------------------------------------
extern "C" void kernel_launch(void* const* d_in, const int* in_sizes, int n_in,
                              void* d_out, int out_size)
{
    const float* values = (const float*)d_in[0];
    const float* key    = (const float*)d_in[1];
    const float* query  = (const float*)d_in[2];
    const int*   mask   = (const int*)d_in[3];
    const float* Wv = (const float*)d_in[4];
    const float* bv = (const float*)d_in[5];
    const float* Wk = (const float*)d_in[6];
    const float* bk = (const float*)d_in[7];
    const float* Wq = (const float*)d_in[8];
    const float* bq = (const float*)d_in[9];
    const float* Wo = (const float*)d_in[10];
    const float* bo = (const float*)d_in[11];
    float* out = (float*)d_out;

    float *Qp, *Kp, *Vp, *AOp;
    cudaGetSymbolAddress((void**)&Qp, g_Q);
    cudaGetSymbolAddress((void**)&Kp, g_K);
    cudaGetSymbolAddress((void**)&Vp, g_V);
    cudaGetSymbolAddress((void**)&AOp, g_AO);

    const int M = NB * L;   // 4096
    dim3 gemm_grid(D / 128, M / 128);   // (8, 32)
    dim3 gemm_blk(256);

    gemm_xWT_bias<<<gemm_grid, gemm_blk>>>(query,  Wq, bq, Qp, M, D, D);
    gemm_xWT_bias<<<gemm_grid, gemm_blk>>>(key,    Wk, bk, Kp, M, D, D);
    gemm_xWT_bias<<<gemm_grid, gemm_blk>>>(values, Wv, bv, Vp, M, D, D);

    dim3 fa_grid(L / 64, H, NB);        // (32, 16, 2)
    flash_attn<<<fa_grid, 256>>>(Qp, Kp, Vp, mask, AOp);

    gemm_xWT_bias<<<gemm_grid, gemm_blk>>>(AOp, Wo, bo, out, M, D, D);
}

// round 4
// speedup vs baseline: 1.4443x; 1.4443x over previous
#include <cuda_runtime.h>
#include <cstdint>
#include <math.h>

// Problem constants
constexpr int NB = 2;      // batch
constexpr int L  = 2048;   // seq len
constexpr int D  = 1024;   // embed dim
constexpr int H  = 16;     // heads
constexpr int HD = 64;     // head dim
constexpr float SM_SCALE = 0.03125f; // 1/sqrt(1024)

// Scratch (device globals: allocation-free rule)
__device__ float g_Q[NB * L * D];
__device__ float g_K[NB * L * D];
__device__ float g_V[NB * L * D];
__device__ float g_AO[NB * L * D];

// ---------------------------------------------------------------------------
// mma.sync tf32 helpers (arch-stable path; tcgen05 is unavailable: the build
// targets sm_103 without the 'a' feature suffix)
// ---------------------------------------------------------------------------
__device__ __forceinline__ uint32_t f2tf32(float f) {
    uint32_t r;
    asm("cvt.rna.tf32.f32 %0, %1;" : "=r"(r) : "f"(f));
    return r;
}

__device__ __forceinline__ void mma_tf32_16x8x8(
    float* d, const uint32_t* a, const uint32_t* b)
{
    asm volatile(
        "mma.sync.aligned.m16n8k8.row.col.f32.tf32.tf32.f32 "
        "{%0,%1,%2,%3}, {%4,%5,%6,%7}, {%8,%9}, {%0,%1,%2,%3};"
        : "+f"(d[0]), "+f"(d[1]), "+f"(d[2]), "+f"(d[3])
        : "r"(a[0]), "r"(a[1]), "r"(a[2]), "r"(a[3]),
          "r"(b[0]), "r"(b[1]));
}

// ---------------------------------------------------------------------------
// TF32 tensor-core GEMM: C[M,1024] = A[M,K=1024] @ W[N=1024,K]^T + bias[N]
// CTA tile 128x128, BK=32, 256 threads (8 warps, 2x4), warp tile 64x32.
// SMEM double-buffered [2][128][36] per operand (pad 36 -> LDS conflict-free).
// Register-staged global prefetch overlaps compute.
// ---------------------------------------------------------------------------
constexpr int BK = 32;
constexpr int LDT = 36;                        // padded tile row stride (floats)
constexpr int TILE_FLOATS = 128 * LDT;         // one buffer
constexpr int GEMM_SMEM_BYTES = 2 * 2 * TILE_FLOATS * 4;   // A+B, 2 buffers: 73728

__global__ __launch_bounds__(256) void gemm_mma_tf32(
    const float* __restrict__ A, const float* __restrict__ W,
    const float* __restrict__ bias, float* __restrict__ C)
{
    extern __shared__ float sm[];
    float* As = sm;                       // [2][128][36]
    float* Bs = sm + 2 * TILE_FLOATS;     // [2][128][36]

    const int tid  = threadIdx.x;
    const int wid  = tid >> 5;
    const int lane = tid & 31;
    const int warp_m = wid & 1;           // 2 -> 64 rows each
    const int warp_n = wid >> 1;          // 4 -> 32 cols each
    const int lr = lane >> 2;             // 0..7
    const int lc = lane & 3;              // 0..3

    const int m0 = blockIdx.y * 128;
    const int n0 = blockIdx.x * 128;

    // Global load coords: per tile 128x32 floats = 1024 float4; 256 thr x 4
    const int grow = tid >> 3;            // 0..31 (+ it*32)
    const int gq   = tid & 7;             // float4 idx within 32-float row
    const float* Abase = A + (size_t)(m0 + grow) * D + gq * 4;
    const float* Wbase = W + (size_t)(n0 + grow) * D + gq * 4;

    float acc[4][4][4];
#pragma unroll
    for (int i = 0; i < 4; i++)
#pragma unroll
        for (int j = 0; j < 4; j++)
#pragma unroll
            for (int r = 0; r < 4; r++) acc[i][j][r] = 0.f;

    float4 areg[4], breg[4];

    // Prologue: load tile 0
#pragma unroll
    for (int it = 0; it < 4; ++it) {
        areg[it] = *(const float4*)(Abase + (size_t)(it * 32) * D);
        breg[it] = *(const float4*)(Wbase + (size_t)(it * 32) * D);
    }
#pragma unroll
    for (int it = 0; it < 4; ++it) {
        const int r = it * 32 + grow;
        float* ap = As + r * LDT + gq * 4;
        float* bp = Bs + r * LDT + gq * 4;
        ap[0] = __uint_as_float(f2tf32(areg[it].x));
        ap[1] = __uint_as_float(f2tf32(areg[it].y));
        ap[2] = __uint_as_float(f2tf32(areg[it].z));
        ap[3] = __uint_as_float(f2tf32(areg[it].w));
        bp[0] = __uint_as_float(f2tf32(breg[it].x));
        bp[1] = __uint_as_float(f2tf32(breg[it].y));
        bp[2] = __uint_as_float(f2tf32(breg[it].z));
        bp[3] = __uint_as_float(f2tf32(breg[it].w));
    }
    __syncthreads();

    const int NKC = D / BK;   // 32
    for (int kc = 0; kc < NKC; ++kc) {
        const int cur = kc & 1;
        const int nxt = cur ^ 1;

        // Prefetch next tile into regs (overlaps with compute below)
        if (kc + 1 < NKC) {
            const int kg = (kc + 1) * BK;
#pragma unroll
            for (int it = 0; it < 4; ++it) {
                areg[it] = *(const float4*)(Abase + (size_t)(it * 32) * D + kg);
                breg[it] = *(const float4*)(Wbase + (size_t)(it * 32) * D + kg);
            }
        }

        // Compute on current buffer: 4 k-steps of 8
        const float* Ab = As + cur * TILE_FLOATS;
        const float* Bb = Bs + cur * TILE_FLOATS;
#pragma unroll
        for (int kk = 0; kk < 4; ++kk) {
            const int c0 = kk * 8 + lc;
            uint32_t af[4][4], bf[4][2];
#pragma unroll
            for (int mi = 0; mi < 4; ++mi) {
                const int r = warp_m * 64 + mi * 16 + lr;
                af[mi][0] = __float_as_uint(Ab[r * LDT + c0]);
                af[mi][1] = __float_as_uint(Ab[(r + 8) * LDT + c0]);
                af[mi][2] = __float_as_uint(Ab[r * LDT + c0 + 4]);
                af[mi][3] = __float_as_uint(Ab[(r + 8) * LDT + c0 + 4]);
            }
#pragma unroll
            for (int ni = 0; ni < 4; ++ni) {
                const int r = warp_n * 32 + ni * 8 + lr;
                bf[ni][0] = __float_as_uint(Bb[r * LDT + c0]);
                bf[ni][1] = __float_as_uint(Bb[r * LDT + c0 + 4]);
            }
#pragma unroll
            for (int mi = 0; mi < 4; ++mi)
#pragma unroll
                for (int ni = 0; ni < 4; ++ni)
                    mma_tf32_16x8x8(acc[mi][ni], af[mi], bf[ni]);
        }

        // Stage prefetched tile into the other buffer
        if (kc + 1 < NKC) {
            float* Ad = As + nxt * TILE_FLOATS;
            float* Bd = Bs + nxt * TILE_FLOATS;
#pragma unroll
            for (int it = 0; it < 4; ++it) {
                const int r = it * 32 + grow;
                float* ap = Ad + r * LDT + gq * 4;
                float* bp = Bd + r * LDT + gq * 4;
                ap[0] = __uint_as_float(f2tf32(areg[it].x));
                ap[1] = __uint_as_float(f2tf32(areg[it].y));
                ap[2] = __uint_as_float(f2tf32(areg[it].z));
                ap[3] = __uint_as_float(f2tf32(areg[it].w));
                bp[0] = __uint_as_float(f2tf32(breg[it].x));
                bp[1] = __uint_as_float(f2tf32(breg[it].y));
                bp[2] = __uint_as_float(f2tf32(breg[it].z));
                bp[3] = __uint_as_float(f2tf32(breg[it].w));
            }
        }
        __syncthreads();
    }

    // Epilogue: fragment layout d0,d1 @ (row, col..col+1); d2,d3 @ (row+8, ...)
#pragma unroll
    for (int mi = 0; mi < 4; ++mi) {
        const int row = m0 + warp_m * 64 + mi * 16 + lr;
#pragma unroll
        for (int ni = 0; ni < 4; ++ni) {
            const int col = n0 + warp_n * 32 + ni * 8 + lc * 2;
            const float b0 = bias[col], b1 = bias[col + 1];
            float2 v0 = make_float2(acc[mi][ni][0] + b0, acc[mi][ni][1] + b1);
            float2 v1 = make_float2(acc[mi][ni][2] + b0, acc[mi][ni][3] + b1);
            *(float2*)(C + (size_t)row * D + col) = v0;
            *(float2*)(C + (size_t)(row + 8) * D + col) = v1;
        }
    }
}

// ---------------------------------------------------------------------------
// Flash attention (fp32, online softmax) — unchanged (passing baseline).
// ---------------------------------------------------------------------------
__global__ __launch_bounds__(256) void flash_attn(
    const float* __restrict__ Q, const float* __restrict__ K,
    const float* __restrict__ V, const int* __restrict__ mask,
    float* __restrict__ O)
{
    constexpr int BQ = 64, BKt = 32;
    __shared__ float Qs[BQ][68];
    __shared__ float Ks[BKt][68];
    __shared__ float Vs[BKt][68];
    __shared__ float Ss[BQ][33];
    __shared__ float m_s[BQ], l_s[BQ], fac[BQ];

    const int tid = threadIdx.x;
    const int tx = tid & 15;
    const int ty = tid >> 4;
    const int qt = blockIdx.x;
    const int h  = blockIdx.y;
    const int n  = blockIdx.z;

    const float* Qb = Q + ((size_t)(n * L) + qt * BQ) * D + h * HD;
    for (int i = tid; i < BQ * 16; i += 256) {
        int r = i >> 4, c = (i & 15) * 4;
        float4 v = *(const float4*)(Qb + (size_t)r * D + c);
        Qs[r][c] = v.x; Qs[r][c + 1] = v.y; Qs[r][c + 2] = v.z; Qs[r][c + 3] = v.w;
    }
    if (tid < BQ) { m_s[tid] = -INFINITY; l_s[tid] = 0.f; }

    float acc[4][4];
#pragma unroll
    for (int i = 0; i < 4; i++)
#pragma unroll
        for (int j = 0; j < 4; j++) acc[i][j] = 0.f;
    __syncthreads();

    const int* mrow = mask + n * L;

    for (int kb = 0; kb < L / BKt; ++kb) {
        const float* Kb = K + ((size_t)(n * L) + kb * BKt) * D + h * HD;
        const float* Vb = V + ((size_t)(n * L) + kb * BKt) * D + h * HD;
        for (int i = tid; i < BKt * 16; i += 256) {
            int r = i >> 4, c = (i & 15) * 4;
            float4 kv = *(const float4*)(Kb + (size_t)r * D + c);
            Ks[r][c] = kv.x; Ks[r][c + 1] = kv.y; Ks[r][c + 2] = kv.z; Ks[r][c + 3] = kv.w;
            float4 vv = *(const float4*)(Vb + (size_t)r * D + c);
            Vs[r][c] = vv.x; Vs[r][c + 1] = vv.y; Vs[r][c + 2] = vv.z; Vs[r][c + 3] = vv.w;
        }
        __syncthreads();

        float s[4][2] = {{0.f, 0.f}, {0.f, 0.f}, {0.f, 0.f}, {0.f, 0.f}};
#pragma unroll
        for (int d0 = 0; d0 < HD; d0 += 4) {
            float a[4][4], b[2][4];
#pragma unroll
            for (int i = 0; i < 4; i++)
                *(float4*)a[i] = *(const float4*)&Qs[ty * 4 + i][d0];
#pragma unroll
            for (int j = 0; j < 2; j++)
                *(float4*)b[j] = *(const float4*)&Ks[tx * 2 + j][d0];
#pragma unroll
            for (int kk = 0; kk < 4; kk++)
#pragma unroll
                for (int i = 0; i < 4; i++)
#pragma unroll
                    for (int j = 0; j < 2; j++)
                        s[i][j] += a[i][kk] * b[j][kk];
        }

#pragma unroll
        for (int j = 0; j < 2; j++) {
            int kpos = kb * BKt + tx * 2 + j;
            bool mz = (mrow[kpos] == 0);
#pragma unroll
            for (int i = 0; i < 4; i++)
                Ss[ty * 4 + i][tx * 2 + j] = (mz ? -1e20f : s[i][j]) * SM_SCALE;
        }
        __syncthreads();

        if (tid < BQ) {
            float mold = m_s[tid];
            float mx = mold;
#pragma unroll
            for (int j = 0; j < BKt; j++) mx = fmaxf(mx, Ss[tid][j]);
            float f = __expf(mold - mx);
            float sum = 0.f;
#pragma unroll
            for (int j = 0; j < BKt; j++) {
                float p = __expf(Ss[tid][j] - mx);
                Ss[tid][j] = p;
                sum += p;
            }
            l_s[tid] = l_s[tid] * f + sum;
            m_s[tid] = mx;
            fac[tid] = f;
        }
        __syncthreads();

#pragma unroll
        for (int i = 0; i < 4; i++) {
            float f = fac[ty * 4 + i];
            acc[i][0] *= f; acc[i][1] *= f; acc[i][2] *= f; acc[i][3] *= f;
        }
#pragma unroll 4
        for (int k = 0; k < BKt; k++) {
            float4 bv = *(const float4*)&Vs[k][tx * 4];
#pragma unroll
            for (int i = 0; i < 4; i++) {
                float p = Ss[ty * 4 + i][k];
                acc[i][0] += p * bv.x; acc[i][1] += p * bv.y;
                acc[i][2] += p * bv.z; acc[i][3] += p * bv.w;
            }
        }
        __syncthreads();
    }

    float* Ob = O + ((size_t)(n * L) + qt * BQ) * D + h * HD;
#pragma unroll
    for (int i = 0; i < 4; i++) {
        int row = ty * 4 + i;
        float inv = 1.0f / l_s[row];
        float4 o = make_float4(acc[i][0] * inv, acc[i][1] * inv,
                               acc[i][2] * inv, acc[i][3] * inv);
        *(float4*)(Ob + (size_t)row * D + tx * 4) = o;
    }
}

// ---------------------------------------------------------------------------
// Launch
// ---------------------------------------------------------------------------
extern "C" void kernel_launch(void* const* d_in, const int* in_sizes, int n_in,
                              void* d_out, int out_size)
{
    const float* values = (const float*)d_in[0];
    const float* key    = (const float*)d_in[1];
    const float* query  = (const float*)d_in[2];
    const int*   mask   = (const int*)d_in[3];
    const float* Wv = (const float*)d_in[4];
    const float* bv = (const float*)d_in[5];
    const float* Wk = (const float*)d_in[6];
    const float* bk = (const float*)d_in[7];
    const float* Wq = (const float*)d_in[8];
    const float* bq = (const float*)d_in[9];
    const float* Wo = (const float*)d_in[10];
    const float* bo = (const float*)d_in[11];
    float* out = (float*)d_out;

    float *Qp, *Kp, *Vp, *AOp;
    cudaGetSymbolAddress((void**)&Qp, g_Q);
    cudaGetSymbolAddress((void**)&Kp, g_K);
    cudaGetSymbolAddress((void**)&Vp, g_V);
    cudaGetSymbolAddress((void**)&AOp, g_AO);

    cudaFuncSetAttribute(gemm_mma_tf32,
                         cudaFuncAttributeMaxDynamicSharedMemorySize,
                         GEMM_SMEM_BYTES);

    dim3 gemm_grid(D / 128, (NB * L) / 128);   // (8, 32)

    gemm_mma_tf32<<<gemm_grid, 256, GEMM_SMEM_BYTES>>>(query,  Wq, bq, Qp);
    gemm_mma_tf32<<<gemm_grid, 256, GEMM_SMEM_BYTES>>>(key,    Wk, bk, Kp);
    gemm_mma_tf32<<<gemm_grid, 256, GEMM_SMEM_BYTES>>>(values, Wv, bv, Vp);

    dim3 fa_grid(L / 64, H, NB);               // (32, 16, 2)
    flash_attn<<<fa_grid, 256>>>(Qp, Kp, Vp, mask, AOp);

    gemm_mma_tf32<<<gemm_grid, 256, GEMM_SMEM_BYTES>>>(AOp, Wo, bo, out);
}

// round 5
// speedup vs baseline: 2.1540x; 1.4914x over previous
#include <cuda_runtime.h>
#include <cstdint>
#include <math.h>

// Problem constants
constexpr int NB = 2;      // batch
constexpr int L  = 2048;   // seq len
constexpr int D  = 1024;   // embed dim
constexpr int H  = 16;     // heads
constexpr int HD = 64;     // head dim
constexpr float SM_SCALE = 0.03125f;      // 1/sqrt(1024)
constexpr float MASK_ADD = -3.125e18f;    // -1e20 * SM_SCALE

// Scratch (device globals: allocation-free rule)
__device__ float g_Q[NB * L * D];
__device__ float g_K[NB * L * D];
__device__ float g_V[NB * L * D];
__device__ float g_AO[NB * L * D];

// ---------------------------------------------------------------------------
// mma.sync tf32 helpers (arch-stable path; tcgen05 unavailable: build targets
// plain sm_103 without the 'a' suffix)
// ---------------------------------------------------------------------------
__device__ __forceinline__ uint32_t f2tf32(float f) {
    uint32_t r;
    asm("cvt.rna.tf32.f32 %0, %1;" : "=r"(r) : "f"(f));
    return r;
}

__device__ __forceinline__ void mma_tf32_16x8x8(
    float* d, const uint32_t* a, const uint32_t* b)
{
    asm volatile(
        "mma.sync.aligned.m16n8k8.row.col.f32.tf32.tf32.f32 "
        "{%0,%1,%2,%3}, {%4,%5,%6,%7}, {%8,%9}, {%0,%1,%2,%3};"
        : "+f"(d[0]), "+f"(d[1]), "+f"(d[2]), "+f"(d[3])
        : "r"(a[0]), "r"(a[1]), "r"(a[2]), "r"(a[3]),
          "r"(b[0]), "r"(b[1]));
}

// ---------------------------------------------------------------------------
// TF32 tensor-core GEMM (unchanged from R4 passing kernel)
// C[M,1024] = A[M,K=1024] @ W[N=1024,K]^T + bias[N]
// ---------------------------------------------------------------------------
constexpr int BK = 32;
constexpr int LDT = 36;
constexpr int TILE_FLOATS = 128 * LDT;
constexpr int GEMM_SMEM_BYTES = 2 * 2 * TILE_FLOATS * 4;

__global__ __launch_bounds__(256) void gemm_mma_tf32(
    const float* __restrict__ A, const float* __restrict__ W,
    const float* __restrict__ bias, float* __restrict__ C)
{
    extern __shared__ float sm[];
    float* As = sm;
    float* Bs = sm + 2 * TILE_FLOATS;

    const int tid  = threadIdx.x;
    const int wid  = tid >> 5;
    const int lane = tid & 31;
    const int warp_m = wid & 1;
    const int warp_n = wid >> 1;
    const int lr = lane >> 2;
    const int lc = lane & 3;

    const int m0 = blockIdx.y * 128;
    const int n0 = blockIdx.x * 128;

    const int grow = tid >> 3;
    const int gq   = tid & 7;
    const float* Abase = A + (size_t)(m0 + grow) * D + gq * 4;
    const float* Wbase = W + (size_t)(n0 + grow) * D + gq * 4;

    float acc[4][4][4];
#pragma unroll
    for (int i = 0; i < 4; i++)
#pragma unroll
        for (int j = 0; j < 4; j++)
#pragma unroll
            for (int r = 0; r < 4; r++) acc[i][j][r] = 0.f;

    float4 areg[4], breg[4];

#pragma unroll
    for (int it = 0; it < 4; ++it) {
        areg[it] = *(const float4*)(Abase + (size_t)(it * 32) * D);
        breg[it] = *(const float4*)(Wbase + (size_t)(it * 32) * D);
    }
#pragma unroll
    for (int it = 0; it < 4; ++it) {
        const int r = it * 32 + grow;
        float* ap = As + r * LDT + gq * 4;
        float* bp = Bs + r * LDT + gq * 4;
        ap[0] = __uint_as_float(f2tf32(areg[it].x));
        ap[1] = __uint_as_float(f2tf32(areg[it].y));
        ap[2] = __uint_as_float(f2tf32(areg[it].z));
        ap[3] = __uint_as_float(f2tf32(areg[it].w));
        bp[0] = __uint_as_float(f2tf32(breg[it].x));
        bp[1] = __uint_as_float(f2tf32(breg[it].y));
        bp[2] = __uint_as_float(f2tf32(breg[it].z));
        bp[3] = __uint_as_float(f2tf32(breg[it].w));
    }
    __syncthreads();

    const int NKC = D / BK;
    for (int kc = 0; kc < NKC; ++kc) {
        const int cur = kc & 1;
        const int nxt = cur ^ 1;

        if (kc + 1 < NKC) {
            const int kg = (kc + 1) * BK;
#pragma unroll
            for (int it = 0; it < 4; ++it) {
                areg[it] = *(const float4*)(Abase + (size_t)(it * 32) * D + kg);
                breg[it] = *(const float4*)(Wbase + (size_t)(it * 32) * D + kg);
            }
        }

        const float* Ab = As + cur * TILE_FLOATS;
        const float* Bb = Bs + cur * TILE_FLOATS;
#pragma unroll
        for (int kk = 0; kk < 4; ++kk) {
            const int c0 = kk * 8 + lc;
            uint32_t af[4][4], bf[4][2];
#pragma unroll
            for (int mi = 0; mi < 4; ++mi) {
                const int r = warp_m * 64 + mi * 16 + lr;
                af[mi][0] = __float_as_uint(Ab[r * LDT + c0]);
                af[mi][1] = __float_as_uint(Ab[(r + 8) * LDT + c0]);
                af[mi][2] = __float_as_uint(Ab[r * LDT + c0 + 4]);
                af[mi][3] = __float_as_uint(Ab[(r + 8) * LDT + c0 + 4]);
            }
#pragma unroll
            for (int ni = 0; ni < 4; ++ni) {
                const int r = warp_n * 32 + ni * 8 + lr;
                bf[ni][0] = __float_as_uint(Bb[r * LDT + c0]);
                bf[ni][1] = __float_as_uint(Bb[r * LDT + c0 + 4]);
            }
#pragma unroll
            for (int mi = 0; mi < 4; ++mi)
#pragma unroll
                for (int ni = 0; ni < 4; ++ni)
                    mma_tf32_16x8x8(acc[mi][ni], af[mi], bf[ni]);
        }

        if (kc + 1 < NKC) {
            float* Ad = As + nxt * TILE_FLOATS;
            float* Bd = Bs + nxt * TILE_FLOATS;
#pragma unroll
            for (int it = 0; it < 4; ++it) {
                const int r = it * 32 + grow;
                float* ap = Ad + r * LDT + gq * 4;
                float* bp = Bd + r * LDT + gq * 4;
                ap[0] = __uint_as_float(f2tf32(areg[it].x));
                ap[1] = __uint_as_float(f2tf32(areg[it].y));
                ap[2] = __uint_as_float(f2tf32(areg[it].z));
                ap[3] = __uint_as_float(f2tf32(areg[it].w));
                bp[0] = __uint_as_float(f2tf32(breg[it].x));
                bp[1] = __uint_as_float(f2tf32(breg[it].y));
                bp[2] = __uint_as_float(f2tf32(breg[it].z));
                bp[3] = __uint_as_float(f2tf32(breg[it].w));
            }
        }
        __syncthreads();
    }

#pragma unroll
    for (int mi = 0; mi < 4; ++mi) {
        const int row = m0 + warp_m * 64 + mi * 16 + lr;
#pragma unroll
        for (int ni = 0; ni < 4; ++ni) {
            const int col = n0 + warp_n * 32 + ni * 8 + lc * 2;
            const float b0 = bias[col], b1 = bias[col + 1];
            float2 v0 = make_float2(acc[mi][ni][0] + b0, acc[mi][ni][1] + b1);
            float2 v1 = make_float2(acc[mi][ni][2] + b0, acc[mi][ni][3] + b1);
            *(float2*)(C + (size_t)row * D + col) = v0;
            *(float2*)(C + (size_t)(row + 8) * D + col) = v1;
        }
    }
}

// ---------------------------------------------------------------------------
// Tensor-core flash attention (tf32 mma, FA2 online softmax in fragments).
// BQ=128 per CTA (8 warps x 16 rows), BK=64 keys per tile, Hd=64.
// Q fragments live in registers for the whole kernel. P stays in registers
// via an intra-quad shfl permute (C-layout -> A-layout).
// ---------------------------------------------------------------------------
constexpr int FA_LDK = 68;   // bank = 4*lr + lc : conflict-free B-frag loads
constexpr int FA_LDV = 72;   // bank = 8*lc + lr : conflict-free B-frag loads
constexpr int FA_LDQ = 68;
constexpr int FA_POOL = 64 * FA_LDK + 64 * FA_LDV;   // 8960 floats

__global__ __launch_bounds__(256) void flash_attn_tc(
    const float* __restrict__ Q, const float* __restrict__ K,
    const float* __restrict__ V, const int* __restrict__ mask,
    float* __restrict__ O)
{
    __shared__ float pool[FA_POOL];
    __shared__ float madd[64];

    float* Ks = pool;
    float* Vs = pool + 64 * FA_LDK;
    float* Qs = pool;                 // reused before main loop

    const int tid  = threadIdx.x;
    const int wid  = tid >> 5;
    const int lane = tid & 31;
    const int lr   = lane >> 2;       // 0..7
    const int lc   = lane & 3;        // 0..3
    const int qt = blockIdx.x;        // 0..15
    const int h  = blockIdx.y;        // 0..15
    const int n  = blockIdx.z;        // 0..1

    // ---- Stage Q tile (128 x 64) into smem, tf32-converted ----
    const float* Qb = Q + ((size_t)(n * L) + qt * 128) * D + h * HD;
#pragma unroll
    for (int it = 0; it < 8; ++it) {
        const int i = it * 256 + tid;
        const int r = i >> 4, c4 = (i & 15) * 4;
        float4 v = *(const float4*)(Qb + (size_t)r * D + c4);
        float* qp = Qs + r * FA_LDQ + c4;
        qp[0] = __uint_as_float(f2tf32(v.x));
        qp[1] = __uint_as_float(f2tf32(v.y));
        qp[2] = __uint_as_float(f2tf32(v.z));
        qp[3] = __uint_as_float(f2tf32(v.w));
    }
    __syncthreads();

    // ---- Extract Q A-fragments into registers (kept all kernel) ----
    uint32_t qf[8][4];
    {
        const int qrow = wid * 16 + lr;
#pragma unroll
        for (int ks = 0; ks < 8; ++ks) {
            const int c0 = ks * 8 + lc;
            qf[ks][0] = __float_as_uint(Qs[qrow * FA_LDQ + c0]);
            qf[ks][1] = __float_as_uint(Qs[(qrow + 8) * FA_LDQ + c0]);
            qf[ks][2] = __float_as_uint(Qs[qrow * FA_LDQ + c0 + 4]);
            qf[ks][3] = __float_as_uint(Qs[(qrow + 8) * FA_LDQ + c0 + 4]);
        }
    }
    __syncthreads();   // pool is about to be overwritten by K/V

    float o[8][4];
#pragma unroll
    for (int i = 0; i < 8; i++)
#pragma unroll
        for (int j = 0; j < 4; j++) o[i][j] = 0.f;
    float m0 = -INFINITY, m1 = -INFINITY, l0 = 0.f, l1 = 0.f;

    const float* Kb0 = K + (size_t)(n * L) * D + h * HD;
    const float* Vb0 = V + (size_t)(n * L) * D + h * HD;
    const int* mrow = mask + n * L;
    const int qbase = lane & 28;

    for (int kb = 0; kb < L / 64; ++kb) {
        // ---- Stage K/V tiles (64 x 64 each), tf32-converted ----
#pragma unroll
        for (int it = 0; it < 4; ++it) {
            const int i = it * 256 + tid;
            const int r = i >> 4, c4 = (i & 15) * 4;
            const size_t goff = (size_t)(kb * 64 + r) * D + c4;
            float4 kv = *(const float4*)(Kb0 + goff);
            float4 vv = *(const float4*)(Vb0 + goff);
            float* kp = Ks + r * FA_LDK + c4;
            kp[0] = __uint_as_float(f2tf32(kv.x));
            kp[1] = __uint_as_float(f2tf32(kv.y));
            kp[2] = __uint_as_float(f2tf32(kv.z));
            kp[3] = __uint_as_float(f2tf32(kv.w));
            float* vp = Vs + r * FA_LDV + c4;
            vp[0] = __uint_as_float(f2tf32(vv.x));
            vp[1] = __uint_as_float(f2tf32(vv.y));
            vp[2] = __uint_as_float(f2tf32(vv.z));
            vp[3] = __uint_as_float(f2tf32(vv.w));
        }
        if (tid < 64)
            madd[tid] = (mrow[kb * 64 + tid] == 0) ? MASK_ADD : 0.f;
        __syncthreads();

        // ---- S = Q @ K^T  (C-fragments sc[nb][4]) ----
        float sc[8][4];
#pragma unroll
        for (int nb = 0; nb < 8; ++nb) {
            sc[nb][0] = sc[nb][1] = sc[nb][2] = sc[nb][3] = 0.f;
            const float* kr = Ks + (nb * 8 + lr) * FA_LDK + lc;
#pragma unroll
            for (int ks = 0; ks < 8; ++ks) {
                uint32_t bf[2];
                bf[0] = __float_as_uint(kr[ks * 8]);
                bf[1] = __float_as_uint(kr[ks * 8 + 4]);
                mma_tf32_16x8x8(sc[nb], qf[ks], bf);
            }
        }

        // ---- mask + scale; row stats over the 64-wide tile ----
        float mloc0 = -INFINITY, mloc1 = -INFINITY;
#pragma unroll
        for (int nb = 0; nb < 8; ++nb) {
            const float ma = madd[nb * 8 + lc * 2];
            const float mb = madd[nb * 8 + lc * 2 + 1];
            sc[nb][0] = fmaf(sc[nb][0], SM_SCALE, ma);
            sc[nb][1] = fmaf(sc[nb][1], SM_SCALE, mb);
            sc[nb][2] = fmaf(sc[nb][2], SM_SCALE, ma);
            sc[nb][3] = fmaf(sc[nb][3], SM_SCALE, mb);
            mloc0 = fmaxf(mloc0, fmaxf(sc[nb][0], sc[nb][1]));
            mloc1 = fmaxf(mloc1, fmaxf(sc[nb][2], sc[nb][3]));
        }
        mloc0 = fmaxf(mloc0, __shfl_xor_sync(0xffffffffu, mloc0, 1));
        mloc0 = fmaxf(mloc0, __shfl_xor_sync(0xffffffffu, mloc0, 2));
        mloc1 = fmaxf(mloc1, __shfl_xor_sync(0xffffffffu, mloc1, 1));
        mloc1 = fmaxf(mloc1, __shfl_xor_sync(0xffffffffu, mloc1, 2));

        const float mn0 = fmaxf(m0, mloc0);
        const float mn1 = fmaxf(m1, mloc1);
        const float f0 = __expf(m0 - mn0);
        const float f1 = __expf(m1 - mn1);

        float s0 = 0.f, s1 = 0.f;
#pragma unroll
        for (int nb = 0; nb < 8; ++nb) {
            sc[nb][0] = __expf(sc[nb][0] - mn0);
            sc[nb][1] = __expf(sc[nb][1] - mn0);
            sc[nb][2] = __expf(sc[nb][2] - mn1);
            sc[nb][3] = __expf(sc[nb][3] - mn1);
            s0 += sc[nb][0] + sc[nb][1];
            s1 += sc[nb][2] + sc[nb][3];
        }
        s0 += __shfl_xor_sync(0xffffffffu, s0, 1);
        s0 += __shfl_xor_sync(0xffffffffu, s0, 2);
        s1 += __shfl_xor_sync(0xffffffffu, s1, 1);
        s1 += __shfl_xor_sync(0xffffffffu, s1, 2);

        l0 = l0 * f0 + s0;
        l1 = l1 * f1 + s1;
        m0 = mn0;
        m1 = mn1;

#pragma unroll
        for (int nb = 0; nb < 8; ++nb) {
            o[nb][0] *= f0; o[nb][1] *= f0;
            o[nb][2] *= f1; o[nb][3] *= f1;
        }

        // ---- O += P @ V : permute C-layout -> A-layout per 8x8 k-block ----
#pragma unroll
        for (int kj = 0; kj < 8; ++kj) {
            const int s_lo = qbase + (lc >> 1);
            const int s_hi = s_lo + 2;
            const float t0 = __shfl_sync(0xffffffffu, sc[kj][0], s_lo);
            const float t1 = __shfl_sync(0xffffffffu, sc[kj][1], s_lo);
            const float u0 = __shfl_sync(0xffffffffu, sc[kj][0], s_hi);
            const float u1 = __shfl_sync(0xffffffffu, sc[kj][1], s_hi);
            const float t2 = __shfl_sync(0xffffffffu, sc[kj][2], s_lo);
            const float t3 = __shfl_sync(0xffffffffu, sc[kj][3], s_lo);
            const float u2 = __shfl_sync(0xffffffffu, sc[kj][2], s_hi);
            const float u3 = __shfl_sync(0xffffffffu, sc[kj][3], s_hi);
            const bool odd = (lc & 1);
            uint32_t pa[4];
            pa[0] = f2tf32(odd ? t1 : t0);
            pa[1] = f2tf32(odd ? t3 : t2);
            pa[2] = f2tf32(odd ? u1 : u0);
            pa[3] = f2tf32(odd ? u3 : u2);

            const float* vr = Vs + (kj * 8 + lc) * FA_LDV + lr;
#pragma unroll
            for (int nb2 = 0; nb2 < 8; ++nb2) {
                uint32_t bf[2];
                bf[0] = __float_as_uint(vr[nb2 * 8]);
                bf[1] = __float_as_uint(vr[4 * FA_LDV + nb2 * 8]);
                mma_tf32_16x8x8(o[nb2], pa, bf);
            }
        }
        __syncthreads();
    }

    // ---- Epilogue: normalize and store ----
    const float inv0 = 1.0f / l0;
    const float inv1 = 1.0f / l1;
    const int row0 = qt * 128 + wid * 16 + lr;
    float* Ob = O + ((size_t)(n * L) + row0) * D + h * HD;
#pragma unroll
    for (int nb = 0; nb < 8; ++nb) {
        const int col = nb * 8 + lc * 2;
        *(float2*)(Ob + col) = make_float2(o[nb][0] * inv0, o[nb][1] * inv0);
        *(float2*)(Ob + (size_t)8 * D + col) = make_float2(o[nb][2] * inv1, o[nb][3] * inv1);
    }
}

// ---------------------------------------------------------------------------
// Launch
// ---------------------------------------------------------------------------
extern "C" void kernel_launch(void* const* d_in, const int* in_sizes, int n_in,
                              void* d_out, int out_size)
{
    const float* values = (const float*)d_in[0];
    const float* key    = (const float*)d_in[1];
    const float* query  = (const float*)d_in[2];
    const int*   mask   = (const int*)d_in[3];
    const float* Wv = (const float*)d_in[4];
    const float* bv = (const float*)d_in[5];
    const float* Wk = (const float*)d_in[6];
    const float* bk = (const float*)d_in[7];
    const float* Wq = (const float*)d_in[8];
    const float* bq = (const float*)d_in[9];
    const float* Wo = (const float*)d_in[10];
    const float* bo = (const float*)d_in[11];
    float* out = (float*)d_out;

    float *Qp, *Kp, *Vp, *AOp;
    cudaGetSymbolAddress((void**)&Qp, g_Q);
    cudaGetSymbolAddress((void**)&Kp, g_K);
    cudaGetSymbolAddress((void**)&Vp, g_V);
    cudaGetSymbolAddress((void**)&AOp, g_AO);

    cudaFuncSetAttribute(gemm_mma_tf32,
                         cudaFuncAttributeMaxDynamicSharedMemorySize,
                         GEMM_SMEM_BYTES);

    dim3 gemm_grid(D / 128, (NB * L) / 128);   // (8, 32)

    gemm_mma_tf32<<<gemm_grid, 256, GEMM_SMEM_BYTES>>>(query,  Wq, bq, Qp);
    gemm_mma_tf32<<<gemm_grid, 256, GEMM_SMEM_BYTES>>>(key,    Wk, bk, Kp);
    gemm_mma_tf32<<<gemm_grid, 256, GEMM_SMEM_BYTES>>>(values, Wv, bv, Vp);

    dim3 fa_grid(L / 128, H, NB);              // (16, 16, 2)
    flash_attn_tc<<<fa_grid, 256>>>(Qp, Kp, Vp, mask, AOp);

    gemm_mma_tf32<<<gemm_grid, 256, GEMM_SMEM_BYTES>>>(AOp, Wo, bo, out);
}

// round 7
// speedup vs baseline: 3.8332x; 1.7796x over previous
#include <cuda_runtime.h>
#include <cstdint>
#include <math.h>

// Problem constants
constexpr int NB = 2;      // batch
constexpr int L  = 2048;   // seq len
constexpr int D  = 1024;   // embed dim
constexpr int H  = 16;     // heads
constexpr int HD = 64;     // head dim
constexpr float SM_SCALE = 0.03125f;      // 1/sqrt(1024)
constexpr float MASK_ADD = -3.125e18f;    // -1e20 * SM_SCALE

// Scratch (device globals: allocation-free rule)
__device__ float g_Q[NB * L * D];
__device__ float g_K[NB * L * D];
__device__ float g_V[NB * L * D];
__device__ float g_AO[NB * L * D];

// ---------------------------------------------------------------------------
// mma.sync tf32 helpers (arch-stable path; tcgen05 unavailable: build targets
// plain sm_103 without the 'a' suffix)
// ---------------------------------------------------------------------------
__device__ __forceinline__ uint32_t f2tf32(float f) {
    uint32_t r;
    asm("cvt.rna.tf32.f32 %0, %1;" : "=r"(r) : "f"(f));
    return r;
}

__device__ __forceinline__ void mma_tf32_16x8x8(
    float* d, const uint32_t* a, const uint32_t* b)
{
    asm volatile(
        "mma.sync.aligned.m16n8k8.row.col.f32.tf32.tf32.f32 "
        "{%0,%1,%2,%3}, {%4,%5,%6,%7}, {%8,%9}, {%0,%1,%2,%3};"
        : "+f"(d[0]), "+f"(d[1]), "+f"(d[2]), "+f"(d[3])
        : "r"(a[0]), "r"(a[1]), "r"(a[2]), "r"(a[3]),
          "r"(b[0]), "r"(b[1]));
}

// ---------------------------------------------------------------------------
// TF32 tensor-core GEMM (unchanged passing kernel)
// C[M,1024] = A[M,K=1024] @ W[N=1024,K]^T + bias[N]
// ---------------------------------------------------------------------------
constexpr int BK = 32;
constexpr int LDT = 36;
constexpr int TILE_FLOATS = 128 * LDT;
constexpr int GEMM_SMEM_BYTES = 2 * 2 * TILE_FLOATS * 4;

__global__ __launch_bounds__(256) void gemm_mma_tf32(
    const float* __restrict__ A, const float* __restrict__ W,
    const float* __restrict__ bias, float* __restrict__ C)
{
    extern __shared__ float sm[];
    float* As = sm;
    float* Bs = sm + 2 * TILE_FLOATS;

    const int tid  = threadIdx.x;
    const int wid  = tid >> 5;
    const int lane = tid & 31;
    const int warp_m = wid & 1;
    const int warp_n = wid >> 1;
    const int lr = lane >> 2;
    const int lc = lane & 3;

    const int m0 = blockIdx.y * 128;
    const int n0 = blockIdx.x * 128;

    const int grow = tid >> 3;
    const int gq   = tid & 7;
    const float* Abase = A + (size_t)(m0 + grow) * D + gq * 4;
    const float* Wbase = W + (size_t)(n0 + grow) * D + gq * 4;

    float acc[4][4][4];
#pragma unroll
    for (int i = 0; i < 4; i++)
#pragma unroll
        for (int j = 0; j < 4; j++)
#pragma unroll
            for (int r = 0; r < 4; r++) acc[i][j][r] = 0.f;

    float4 areg[4], breg[4];

#pragma unroll
    for (int it = 0; it < 4; ++it) {
        areg[it] = *(const float4*)(Abase + (size_t)(it * 32) * D);
        breg[it] = *(const float4*)(Wbase + (size_t)(it * 32) * D);
    }
#pragma unroll
    for (int it = 0; it < 4; ++it) {
        const int r = it * 32 + grow;
        float* ap = As + r * LDT + gq * 4;
        float* bp = Bs + r * LDT + gq * 4;
        ap[0] = __uint_as_float(f2tf32(areg[it].x));
        ap[1] = __uint_as_float(f2tf32(areg[it].y));
        ap[2] = __uint_as_float(f2tf32(areg[it].z));
        ap[3] = __uint_as_float(f2tf32(areg[it].w));
        bp[0] = __uint_as_float(f2tf32(breg[it].x));
        bp[1] = __uint_as_float(f2tf32(breg[it].y));
        bp[2] = __uint_as_float(f2tf32(breg[it].z));
        bp[3] = __uint_as_float(f2tf32(breg[it].w));
    }
    __syncthreads();

    const int NKC = D / BK;
    for (int kc = 0; kc < NKC; ++kc) {
        const int cur = kc & 1;
        const int nxt = cur ^ 1;

        if (kc + 1 < NKC) {
            const int kg = (kc + 1) * BK;
#pragma unroll
            for (int it = 0; it < 4; ++it) {
                areg[it] = *(const float4*)(Abase + (size_t)(it * 32) * D + kg);
                breg[it] = *(const float4*)(Wbase + (size_t)(it * 32) * D + kg);
            }
        }

        const float* Ab = As + cur * TILE_FLOATS;
        const float* Bb = Bs + cur * TILE_FLOATS;
#pragma unroll
        for (int kk = 0; kk < 4; ++kk) {
            const int c0 = kk * 8 + lc;
            uint32_t af[4][4], bf[4][2];
#pragma unroll
            for (int mi = 0; mi < 4; ++mi) {
                const int r = warp_m * 64 + mi * 16 + lr;
                af[mi][0] = __float_as_uint(Ab[r * LDT + c0]);
                af[mi][1] = __float_as_uint(Ab[(r + 8) * LDT + c0]);
                af[mi][2] = __float_as_uint(Ab[r * LDT + c0 + 4]);
                af[mi][3] = __float_as_uint(Ab[(r + 8) * LDT + c0 + 4]);
            }
#pragma unroll
            for (int ni = 0; ni < 4; ++ni) {
                const int r = warp_n * 32 + ni * 8 + lr;
                bf[ni][0] = __float_as_uint(Bb[r * LDT + c0]);
                bf[ni][1] = __float_as_uint(Bb[r * LDT + c0 + 4]);
            }
#pragma unroll
            for (int mi = 0; mi < 4; ++mi)
#pragma unroll
                for (int ni = 0; ni < 4; ++ni)
                    mma_tf32_16x8x8(acc[mi][ni], af[mi], bf[ni]);
        }

        if (kc + 1 < NKC) {
            float* Ad = As + nxt * TILE_FLOATS;
            float* Bd = Bs + nxt * TILE_FLOATS;
#pragma unroll
            for (int it = 0; it < 4; ++it) {
                const int r = it * 32 + grow;
                float* ap = Ad + r * LDT + gq * 4;
                float* bp = Bd + r * LDT + gq * 4;
                ap[0] = __uint_as_float(f2tf32(areg[it].x));
                ap[1] = __uint_as_float(f2tf32(areg[it].y));
                ap[2] = __uint_as_float(f2tf32(areg[it].z));
                ap[3] = __uint_as_float(f2tf32(areg[it].w));
                bp[0] = __uint_as_float(f2tf32(breg[it].x));
                bp[1] = __uint_as_float(f2tf32(breg[it].y));
                bp[2] = __uint_as_float(f2tf32(breg[it].z));
                bp[3] = __uint_as_float(f2tf32(breg[it].w));
            }
        }
        __syncthreads();
    }

#pragma unroll
    for (int mi = 0; mi < 4; ++mi) {
        const int row = m0 + warp_m * 64 + mi * 16 + lr;
#pragma unroll
        for (int ni = 0; ni < 4; ++ni) {
            const int col = n0 + warp_n * 32 + ni * 8 + lc * 2;
            const float b0 = bias[col], b1 = bias[col + 1];
            float2 v0 = make_float2(acc[mi][ni][0] + b0, acc[mi][ni][1] + b1);
            float2 v1 = make_float2(acc[mi][ni][2] + b0, acc[mi][ni][3] + b1);
            *(float2*)(C + (size_t)row * D + col) = v0;
            *(float2*)(C + (size_t)(row + 8) * D + col) = v1;
        }
    }
}

// ---------------------------------------------------------------------------
// Tensor-core flash attention (tf32 mma, FA2 online softmax in fragments).
// BQ=128 per CTA (8 warps x 16 rows), BK=64 keys per tile, Hd=64.
// R5 change: Q tile stays resident in SMEM (own region); Q fragments are
// re-loaded per tile so their registers die after the S-phase. This cuts
// regs below 128 -> 2 CTAs/SM (was 148 regs -> 1 CTA/SM, occ 12.4%).
// ---------------------------------------------------------------------------
constexpr int FA_LDQ = 68;   // bank = 4*lr + lc : conflict-free A-frag loads
constexpr int FA_LDK = 68;   // bank = 4*lr + lc : conflict-free B-frag loads
constexpr int FA_LDV = 72;   // bank = 8*lc + lr : conflict-free B-frag loads
constexpr int FA_SMEM_FLOATS = 128 * FA_LDQ + 64 * FA_LDK + 64 * FA_LDV + 64;
constexpr int FA_SMEM_BYTES = FA_SMEM_FLOATS * 4;   // 70912 -> 2 CTAs/SM

__global__ __launch_bounds__(256, 2) void flash_attn_tc(
    const float* __restrict__ Q, const float* __restrict__ K,
    const float* __restrict__ V, const int* __restrict__ mask,
    float* __restrict__ O)
{
    extern __shared__ float fsm[];
    float* Qs = fsm;
    float* Ks = fsm + 128 * FA_LDQ;
    float* Vs = Ks + 64 * FA_LDK;
    float* madd = Vs + 64 * FA_LDV;

    const int tid  = threadIdx.x;
    const int wid  = tid >> 5;
    const int lane = tid & 31;
    const int lr   = lane >> 2;       // 0..7
    const int lc   = lane & 3;        // 0..3
    const int qt = blockIdx.x;        // 0..15
    const int h  = blockIdx.y;        // 0..15
    const int n  = blockIdx.z;        // 0..1

    // ---- Stage Q tile (128 x 64) into smem, tf32-converted; stays resident ----
    const float* Qb = Q + ((size_t)(n * L) + qt * 128) * D + h * HD;
#pragma unroll
    for (int it = 0; it < 8; ++it) {
        const int i = it * 256 + tid;
        const int r = i >> 4, c4 = (i & 15) * 4;
        float4 v = *(const float4*)(Qb + (size_t)r * D + c4);
        float* qp = Qs + r * FA_LDQ + c4;
        qp[0] = __uint_as_float(f2tf32(v.x));
        qp[1] = __uint_as_float(f2tf32(v.y));
        qp[2] = __uint_as_float(f2tf32(v.z));
        qp[3] = __uint_as_float(f2tf32(v.w));
    }
    __syncthreads();

    float o[8][4];
#pragma unroll
    for (int i = 0; i < 8; i++)
#pragma unroll
        for (int j = 0; j < 4; j++) o[i][j] = 0.f;
    float m0 = -INFINITY, m1 = -INFINITY, l0 = 0.f, l1 = 0.f;

    const float* Kb0 = K + (size_t)(n * L) * D + h * HD;
    const float* Vb0 = V + (size_t)(n * L) * D + h * HD;
    const int* mrow = mask + n * L;
    const int qbase = lane & 28;
    const int qrow = wid * 16 + lr;

    for (int kb = 0; kb < L / 64; ++kb) {
        // ---- Stage K/V tiles (64 x 64 each), tf32-converted ----
#pragma unroll
        for (int it = 0; it < 4; ++it) {
            const int i = it * 256 + tid;
            const int r = i >> 4, c4 = (i & 15) * 4;
            const size_t goff = (size_t)(kb * 64 + r) * D + c4;
            float4 kv = *(const float4*)(Kb0 + goff);
            float4 vv = *(const float4*)(Vb0 + goff);
            float* kp = Ks + r * FA_LDK + c4;
            kp[0] = __uint_as_float(f2tf32(kv.x));
            kp[1] = __uint_as_float(f2tf32(kv.y));
            kp[2] = __uint_as_float(f2tf32(kv.z));
            kp[3] = __uint_as_float(f2tf32(kv.w));
            float* vp = Vs + r * FA_LDV + c4;
            vp[0] = __uint_as_float(f2tf32(vv.x));
            vp[1] = __uint_as_float(f2tf32(vv.y));
            vp[2] = __uint_as_float(f2tf32(vv.z));
            vp[3] = __uint_as_float(f2tf32(vv.w));
        }
        if (tid < 64)
            madd[tid] = (mrow[kb * 64 + tid] == 0) ? MASK_ADD : 0.f;

        // ---- Re-load Q A-fragments (Qs stable; overlaps barrier wait) ----
        uint32_t qf[8][4];
#pragma unroll
        for (int ks = 0; ks < 8; ++ks) {
            const int c0 = ks * 8 + lc;
            qf[ks][0] = __float_as_uint(Qs[qrow * FA_LDQ + c0]);
            qf[ks][1] = __float_as_uint(Qs[(qrow + 8) * FA_LDQ + c0]);
            qf[ks][2] = __float_as_uint(Qs[qrow * FA_LDQ + c0 + 4]);
            qf[ks][3] = __float_as_uint(Qs[(qrow + 8) * FA_LDQ + c0 + 4]);
        }
        __syncthreads();

        // ---- S = Q @ K^T  (C-fragments sc[nb][4]) ----
        float sc[8][4];
#pragma unroll
        for (int nb = 0; nb < 8; ++nb) {
            sc[nb][0] = sc[nb][1] = sc[nb][2] = sc[nb][3] = 0.f;
            const float* kr = Ks + (nb * 8 + lr) * FA_LDK + lc;
#pragma unroll
            for (int ks = 0; ks < 8; ++ks) {
                uint32_t bf[2];
                bf[0] = __float_as_uint(kr[ks * 8]);
                bf[1] = __float_as_uint(kr[ks * 8 + 4]);
                mma_tf32_16x8x8(sc[nb], qf[ks], bf);
            }
        }

        // ---- mask + scale; row stats over the 64-wide tile ----
        float mloc0 = -INFINITY, mloc1 = -INFINITY;
#pragma unroll
        for (int nb = 0; nb < 8; ++nb) {
            const float ma = madd[nb * 8 + lc * 2];
            const float mb = madd[nb * 8 + lc * 2 + 1];
            sc[nb][0] = fmaf(sc[nb][0], SM_SCALE, ma);
            sc[nb][1] = fmaf(sc[nb][1], SM_SCALE, mb);
            sc[nb][2] = fmaf(sc[nb][2], SM_SCALE, ma);
            sc[nb][3] = fmaf(sc[nb][3], SM_SCALE, mb);
            mloc0 = fmaxf(mloc0, fmaxf(sc[nb][0], sc[nb][1]));
            mloc1 = fmaxf(mloc1, fmaxf(sc[nb][2], sc[nb][3]));
        }
        mloc0 = fmaxf(mloc0, __shfl_xor_sync(0xffffffffu, mloc0, 1));
        mloc0 = fmaxf(mloc0, __shfl_xor_sync(0xffffffffu, mloc0, 2));
        mloc1 = fmaxf(mloc1, __shfl_xor_sync(0xffffffffu, mloc1, 1));
        mloc1 = fmaxf(mloc1, __shfl_xor_sync(0xffffffffu, mloc1, 2));

        const float mn0 = fmaxf(m0, mloc0);
        const float mn1 = fmaxf(m1, mloc1);
        const float f0 = __expf(m0 - mn0);
        const float f1 = __expf(m1 - mn1);

        float s0 = 0.f, s1 = 0.f;
#pragma unroll
        for (int nb = 0; nb < 8; ++nb) {
            sc[nb][0] = __expf(sc[nb][0] - mn0);
            sc[nb][1] = __expf(sc[nb][1] - mn0);
            sc[nb][2] = __expf(sc[nb][2] - mn1);
            sc[nb][3] = __expf(sc[nb][3] - mn1);
            s0 += sc[nb][0] + sc[nb][1];
            s1 += sc[nb][2] + sc[nb][3];
        }
        s0 += __shfl_xor_sync(0xffffffffu, s0, 1);
        s0 += __shfl_xor_sync(0xffffffffu, s0, 2);
        s1 += __shfl_xor_sync(0xffffffffu, s1, 1);
        s1 += __shfl_xor_sync(0xffffffffu, s1, 2);

        l0 = l0 * f0 + s0;
        l1 = l1 * f1 + s1;
        m0 = mn0;
        m1 = mn1;

#pragma unroll
        for (int nb = 0; nb < 8; ++nb) {
            o[nb][0] *= f0; o[nb][1] *= f0;
            o[nb][2] *= f1; o[nb][3] *= f1;
        }

        // ---- O += P @ V : permute C-layout -> A-layout per 8x8 k-block ----
#pragma unroll
        for (int kj = 0; kj < 8; ++kj) {
            const int s_lo = qbase + (lc >> 1);
            const int s_hi = s_lo + 2;
            const float t0 = __shfl_sync(0xffffffffu, sc[kj][0], s_lo);
            const float t1 = __shfl_sync(0xffffffffu, sc[kj][1], s_lo);
            const float u0 = __shfl_sync(0xffffffffu, sc[kj][0], s_hi);
            const float u1 = __shfl_sync(0xffffffffu, sc[kj][1], s_hi);
            const float t2 = __shfl_sync(0xffffffffu, sc[kj][2], s_lo);
            const float t3 = __shfl_sync(0xffffffffu, sc[kj][3], s_lo);
            const float u2 = __shfl_sync(0xffffffffu, sc[kj][2], s_hi);
            const float u3 = __shfl_sync(0xffffffffu, sc[kj][3], s_hi);
            const bool odd = (lc & 1);
            uint32_t pa[4];
            pa[0] = f2tf32(odd ? t1 : t0);
            pa[1] = f2tf32(odd ? t3 : t2);
            pa[2] = f2tf32(odd ? u1 : u0);
            pa[3] = f2tf32(odd ? u3 : u2);

            const float* vr = Vs + (kj * 8 + lc) * FA_LDV + lr;
#pragma unroll
            for (int nb2 = 0; nb2 < 8; ++nb2) {
                uint32_t bf[2];
                bf[0] = __float_as_uint(vr[nb2 * 8]);
                bf[1] = __float_as_uint(vr[4 * FA_LDV + nb2 * 8]);
                mma_tf32_16x8x8(o[nb2], pa, bf);
            }
        }
        __syncthreads();
    }

    // ---- Epilogue: normalize and store ----
    const float inv0 = 1.0f / l0;
    const float inv1 = 1.0f / l1;
    const int row0 = qt * 128 + wid * 16 + lr;
    float* Ob = O + ((size_t)(n * L) + row0) * D + h * HD;
#pragma unroll
    for (int nb = 0; nb < 8; ++nb) {
        const int col = nb * 8 + lc * 2;
        *(float2*)(Ob + col) = make_float2(o[nb][0] * inv0, o[nb][1] * inv0);
        *(float2*)(Ob + (size_t)8 * D + col) = make_float2(o[nb][2] * inv1, o[nb][3] * inv1);
    }
}

// ---------------------------------------------------------------------------
// Launch
// ---------------------------------------------------------------------------
extern "C" void kernel_launch(void* const* d_in, const int* in_sizes, int n_in,
                              void* d_out, int out_size)
{
    const float* values = (const float*)d_in[0];
    const float* key    = (const float*)d_in[1];
    const float* query  = (const float*)d_in[2];
    const int*   mask   = (const int*)d_in[3];
    const float* Wv = (const float*)d_in[4];
    const float* bv = (const float*)d_in[5];
    const float* Wk = (const float*)d_in[6];
    const float* bk = (const float*)d_in[7];
    const float* Wq = (const float*)d_in[8];
    const float* bq = (const float*)d_in[9];
    const float* Wo = (const float*)d_in[10];
    const float* bo = (const float*)d_in[11];
    float* out = (float*)d_out;

    float *Qp, *Kp, *Vp, *AOp;
    cudaGetSymbolAddress((void**)&Qp, g_Q);
    cudaGetSymbolAddress((void**)&Kp, g_K);
    cudaGetSymbolAddress((void**)&Vp, g_V);
    cudaGetSymbolAddress((void**)&AOp, g_AO);

    cudaFuncSetAttribute(gemm_mma_tf32,
                         cudaFuncAttributeMaxDynamicSharedMemorySize,
                         GEMM_SMEM_BYTES);
    cudaFuncSetAttribute(flash_attn_tc,
                         cudaFuncAttributeMaxDynamicSharedMemorySize,
                         FA_SMEM_BYTES);

    dim3 gemm_grid(D / 128, (NB * L) / 128);   // (8, 32)

    gemm_mma_tf32<<<gemm_grid, 256, GEMM_SMEM_BYTES>>>(query,  Wq, bq, Qp);
    gemm_mma_tf32<<<gemm_grid, 256, GEMM_SMEM_BYTES>>>(key,    Wk, bk, Kp);
    gemm_mma_tf32<<<gemm_grid, 256, GEMM_SMEM_BYTES>>>(values, Wv, bv, Vp);

    dim3 fa_grid(L / 128, H, NB);              // (16, 16, 2)
    flash_attn_tc<<<fa_grid, 256, FA_SMEM_BYTES>>>(Qp, Kp, Vp, mask, AOp);

    gemm_mma_tf32<<<gemm_grid, 256, GEMM_SMEM_BYTES>>>(AOp, Wo, bo, out);
}

// round 8
// speedup vs baseline: 3.8881x; 1.0143x over previous
#include <cuda_runtime.h>
#include <cstdint>
#include <math.h>

// Problem constants
constexpr int NB = 2;      // batch
constexpr int L  = 2048;   // seq len
constexpr int D  = 1024;   // embed dim
constexpr int H  = 16;     // heads
constexpr int HD = 64;     // head dim
constexpr float SM_SCALE = 0.03125f;      // 1/sqrt(1024)
constexpr float MASK_ADD = -3.125e18f;    // -1e20 * SM_SCALE

// Scratch (device globals: allocation-free rule)
__device__ float g_Q[NB * L * D];
__device__ float g_K[NB * L * D];
__device__ float g_V[NB * L * D];
__device__ float g_AO[NB * L * D];
// tf32-preconverted operands
__device__ float g_CV[NB * L * D];
__device__ float g_CK[NB * L * D];
__device__ float g_CQ[NB * L * D];
__device__ float g_CWv[D * D];
__device__ float g_CWk[D * D];
__device__ float g_CWq[D * D];
__device__ float g_CWo[D * D];

// ---------------------------------------------------------------------------
// helpers (arch-stable path; tcgen05 unavailable: build targets plain sm_103)
// ---------------------------------------------------------------------------
__device__ __forceinline__ uint32_t f2tf32(float f) {
    uint32_t r;
    asm("cvt.rna.tf32.f32 %0, %1;" : "=r"(r) : "f"(f));
    return r;
}

__device__ __forceinline__ void mma_tf32_16x8x8(
    float* d, const uint32_t* a, const uint32_t* b)
{
    asm volatile(
        "mma.sync.aligned.m16n8k8.row.col.f32.tf32.tf32.f32 "
        "{%0,%1,%2,%3}, {%4,%5,%6,%7}, {%8,%9}, {%0,%1,%2,%3};"
        : "+f"(d[0]), "+f"(d[1]), "+f"(d[2]), "+f"(d[3])
        : "r"(a[0]), "r"(a[1]), "r"(a[2]), "r"(a[3]),
          "r"(b[0]), "r"(b[1]));
}

__device__ __forceinline__ uint32_t smem_u32(const void* p) {
    uint32_t a;
    asm("{ .reg .u64 t; cvta.to.shared.u64 t, %1; cvt.u32.u64 %0, t; }"
        : "=r"(a) : "l"(p));
    return a;
}

__device__ __forceinline__ void cp_async16(uint32_t saddr, const void* g) {
    asm volatile("cp.async.cg.shared.global [%0], [%1], 16;"
                 :: "r"(saddr), "l"(g) : "memory");
}
__device__ __forceinline__ void cp_commit() {
    asm volatile("cp.async.commit_group;" ::: "memory");
}
template <int N> __device__ __forceinline__ void cp_wait() {
    asm volatile("cp.async.wait_group %0;" :: "n"(N) : "memory");
}

// ---------------------------------------------------------------------------
// One-shot tf32 rounding of all GEMM operands (3 inputs + 4 weights).
// ---------------------------------------------------------------------------
__global__ __launch_bounds__(256) void cvt_all(
    const float4* v, const float4* k, const float4* q,
    const float4* wv, const float4* wk, const float4* wq, const float4* wo,
    float4* cv, float4* ck, float4* cq,
    float4* cwv, float4* cwk, float4* cwq, float4* cwo)
{
    constexpr unsigned X = (NB * L * D) / 4;   // 1M float4
    constexpr unsigned Wn = (D * D) / 4;       // 256K float4
    unsigned t = blockIdx.x * 256u + threadIdx.x;
    const float4* ip; float4* op; unsigned off;
    if (t < X)            { ip = v;  op = cv;  off = t; }
    else if (t < 2 * X)   { ip = k;  op = ck;  off = t - X; }
    else if (t < 3 * X)   { ip = q;  op = cq;  off = t - 2 * X; }
    else if (t < 3 * X + Wn)     { ip = wv; op = cwv; off = t - 3 * X; }
    else if (t < 3 * X + 2 * Wn) { ip = wk; op = cwk; off = t - 3 * X - Wn; }
    else if (t < 3 * X + 3 * Wn) { ip = wq; op = cwq; off = t - 3 * X - 2 * Wn; }
    else                          { ip = wo; op = cwo; off = t - 3 * X - 3 * Wn; }
    float4 x = ip[off];
    x.x = __uint_as_float(f2tf32(x.x));
    x.y = __uint_as_float(f2tf32(x.y));
    x.z = __uint_as_float(f2tf32(x.z));
    x.w = __uint_as_float(f2tf32(x.w));
    op[off] = x;
}

// ---------------------------------------------------------------------------
// TF32 GEMM, cp.async pipeline: C[M,1024] = A[M,K] @ W[N,K]^T + bias[N]
// CTA tile 128x256, BK=32, 256 threads (8 warps, 2x4), warp tile 64x64.
// Operands are pre-rounded to tf32 values; no conversion in the hot loop.
// Grid (4, 32) = 128 CTAs -> single wave.
// ---------------------------------------------------------------------------
constexpr int G_LD = 36;                      // padded row stride (floats)
constexpr int G_ATILE = 128 * G_LD;           // floats per A buffer
constexpr int G_BTILE = 256 * G_LD;           // floats per B buffer
constexpr int G_SMEM_BYTES = 2 * (G_ATILE + G_BTILE) * 4;   // 110592

__global__ __launch_bounds__(256) void gemm_cp(
    const float* __restrict__ A, const float* __restrict__ W,
    const float* __restrict__ bias, float* __restrict__ C)
{
    extern __shared__ float sm[];

    const int tid  = threadIdx.x;
    const int wid  = tid >> 5;
    const int lane = tid & 31;
    const int wm = wid >> 2;          // 0..1
    const int wn = wid & 3;           // 0..3
    const int lr = lane >> 2;         // 0..7
    const int lc = lane & 3;          // 0..3
    const int m0 = blockIdx.y * 128;
    const int n0 = blockIdx.x * 256;
    const uint32_t sb = smem_u32(sm);

    const float* Ag = A + (size_t)m0 * D;
    const float* Wg = W + (size_t)n0 * D;

    auto stage = [&](int buf, int kg) {
#pragma unroll
        for (int i = 0; i < 4; ++i) {           // A: 1024 chunks / 256 thr
            const int idx = i * 256 + tid, r = idx >> 3, q = idx & 7;
            const uint32_t s = sb + (uint32_t)(buf * G_ATILE + r * G_LD + q * 4) * 4u;
            cp_async16(s, Ag + (size_t)r * D + kg + q * 4);
        }
#pragma unroll
        for (int i = 0; i < 8; ++i) {           // B: 2048 chunks / 256 thr
            const int idx = i * 256 + tid, r = idx >> 3, q = idx & 7;
            const uint32_t s = sb + (uint32_t)(2 * G_ATILE + buf * G_BTILE + r * G_LD + q * 4) * 4u;
            cp_async16(s, Wg + (size_t)r * D + kg + q * 4);
        }
    };

    float acc[4][8][4];
#pragma unroll
    for (int i = 0; i < 4; i++)
#pragma unroll
        for (int j = 0; j < 8; j++)
#pragma unroll
            for (int r = 0; r < 4; r++) acc[i][j][r] = 0.f;

    stage(0, 0);  cp_commit();
    stage(1, 32); cp_commit();

    for (int kc = 0; kc < 32; ++kc) {
        cp_wait<1>();
        __syncthreads();

        const float* Ab = sm + (kc & 1) * G_ATILE;
        const float* Bb = sm + 2 * G_ATILE + (kc & 1) * G_BTILE;
#pragma unroll
        for (int kk = 0; kk < 4; ++kk) {
            const int c0 = kk * 8 + lc;
            uint32_t af[4][4], bf[8][2];
#pragma unroll
            for (int mi = 0; mi < 4; ++mi) {
                const int r = wm * 64 + mi * 16 + lr;
                af[mi][0] = __float_as_uint(Ab[r * G_LD + c0]);
                af[mi][1] = __float_as_uint(Ab[(r + 8) * G_LD + c0]);
                af[mi][2] = __float_as_uint(Ab[r * G_LD + c0 + 4]);
                af[mi][3] = __float_as_uint(Ab[(r + 8) * G_LD + c0 + 4]);
            }
#pragma unroll
            for (int ni = 0; ni < 8; ++ni) {
                const int r = wn * 64 + ni * 8 + lr;
                bf[ni][0] = __float_as_uint(Bb[r * G_LD + c0]);
                bf[ni][1] = __float_as_uint(Bb[r * G_LD + c0 + 4]);
            }
#pragma unroll
            for (int mi = 0; mi < 4; ++mi)
#pragma unroll
                for (int ni = 0; ni < 8; ++ni)
                    mma_tf32_16x8x8(acc[mi][ni], af[mi], bf[ni]);
        }
        __syncthreads();
        if (kc + 2 < 32) stage(kc & 1, (kc + 2) * 32);
        cp_commit();   // empty groups keep wait_group accounting exact
    }

    // Epilogue with bias
#pragma unroll
    for (int mi = 0; mi < 4; ++mi) {
        const int row = m0 + wm * 64 + mi * 16 + lr;
#pragma unroll
        for (int ni = 0; ni < 8; ++ni) {
            const int col = n0 + wn * 64 + ni * 8 + lc * 2;
            const float b0 = bias[col], b1 = bias[col + 1];
            *(float2*)(C + (size_t)row * D + col) =
                make_float2(acc[mi][ni][0] + b0, acc[mi][ni][1] + b1);
            *(float2*)(C + (size_t)(row + 8) * D + col) =
                make_float2(acc[mi][ni][2] + b0, acc[mi][ni][3] + b1);
        }
    }
}

// ---------------------------------------------------------------------------
// Tensor-core flash attention (unchanged except epilogue writes tf32-rounded
// AO, replacing the conversion the output GEMM used to do -- identical math).
// ---------------------------------------------------------------------------
constexpr int FA_LDQ = 68;
constexpr int FA_LDK = 68;
constexpr int FA_LDV = 72;
constexpr int FA_SMEM_FLOATS = 128 * FA_LDQ + 64 * FA_LDK + 64 * FA_LDV + 64;
constexpr int FA_SMEM_BYTES = FA_SMEM_FLOATS * 4;   // 70912 -> 2 CTAs/SM

__global__ __launch_bounds__(256, 2) void flash_attn_tc(
    const float* __restrict__ Q, const float* __restrict__ K,
    const float* __restrict__ V, const int* __restrict__ mask,
    float* __restrict__ O)
{
    extern __shared__ float fsm[];
    float* Qs = fsm;
    float* Ks = fsm + 128 * FA_LDQ;
    float* Vs = Ks + 64 * FA_LDK;
    float* madd = Vs + 64 * FA_LDV;

    const int tid  = threadIdx.x;
    const int wid  = tid >> 5;
    const int lane = tid & 31;
    const int lr   = lane >> 2;
    const int lc   = lane & 3;
    const int qt = blockIdx.x;
    const int h  = blockIdx.y;
    const int n  = blockIdx.z;

    const float* Qb = Q + ((size_t)(n * L) + qt * 128) * D + h * HD;
#pragma unroll
    for (int it = 0; it < 8; ++it) {
        const int i = it * 256 + tid;
        const int r = i >> 4, c4 = (i & 15) * 4;
        float4 v = *(const float4*)(Qb + (size_t)r * D + c4);
        float* qp = Qs + r * FA_LDQ + c4;
        qp[0] = __uint_as_float(f2tf32(v.x));
        qp[1] = __uint_as_float(f2tf32(v.y));
        qp[2] = __uint_as_float(f2tf32(v.z));
        qp[3] = __uint_as_float(f2tf32(v.w));
    }
    __syncthreads();

    float o[8][4];
#pragma unroll
    for (int i = 0; i < 8; i++)
#pragma unroll
        for (int j = 0; j < 4; j++) o[i][j] = 0.f;
    float m0 = -INFINITY, m1 = -INFINITY, l0 = 0.f, l1 = 0.f;

    const float* Kb0 = K + (size_t)(n * L) * D + h * HD;
    const float* Vb0 = V + (size_t)(n * L) * D + h * HD;
    const int* mrow = mask + n * L;
    const int qbase = lane & 28;
    const int qrow = wid * 16 + lr;

    for (int kb = 0; kb < L / 64; ++kb) {
#pragma unroll
        for (int it = 0; it < 4; ++it) {
            const int i = it * 256 + tid;
            const int r = i >> 4, c4 = (i & 15) * 4;
            const size_t goff = (size_t)(kb * 64 + r) * D + c4;
            float4 kv = *(const float4*)(Kb0 + goff);
            float4 vv = *(const float4*)(Vb0 + goff);
            float* kp = Ks + r * FA_LDK + c4;
            kp[0] = __uint_as_float(f2tf32(kv.x));
            kp[1] = __uint_as_float(f2tf32(kv.y));
            kp[2] = __uint_as_float(f2tf32(kv.z));
            kp[3] = __uint_as_float(f2tf32(kv.w));
            float* vp = Vs + r * FA_LDV + c4;
            vp[0] = __uint_as_float(f2tf32(vv.x));
            vp[1] = __uint_as_float(f2tf32(vv.y));
            vp[2] = __uint_as_float(f2tf32(vv.z));
            vp[3] = __uint_as_float(f2tf32(vv.w));
        }
        if (tid < 64)
            madd[tid] = (mrow[kb * 64 + tid] == 0) ? MASK_ADD : 0.f;

        uint32_t qf[8][4];
#pragma unroll
        for (int ks = 0; ks < 8; ++ks) {
            const int c0 = ks * 8 + lc;
            qf[ks][0] = __float_as_uint(Qs[qrow * FA_LDQ + c0]);
            qf[ks][1] = __float_as_uint(Qs[(qrow + 8) * FA_LDQ + c0]);
            qf[ks][2] = __float_as_uint(Qs[qrow * FA_LDQ + c0 + 4]);
            qf[ks][3] = __float_as_uint(Qs[(qrow + 8) * FA_LDQ + c0 + 4]);
        }
        __syncthreads();

        float sc[8][4];
#pragma unroll
        for (int nb = 0; nb < 8; ++nb) {
            sc[nb][0] = sc[nb][1] = sc[nb][2] = sc[nb][3] = 0.f;
            const float* kr = Ks + (nb * 8 + lr) * FA_LDK + lc;
#pragma unroll
            for (int ks = 0; ks < 8; ++ks) {
                uint32_t bf[2];
                bf[0] = __float_as_uint(kr[ks * 8]);
                bf[1] = __float_as_uint(kr[ks * 8 + 4]);
                mma_tf32_16x8x8(sc[nb], qf[ks], bf);
            }
        }

        float mloc0 = -INFINITY, mloc1 = -INFINITY;
#pragma unroll
        for (int nb = 0; nb < 8; ++nb) {
            const float ma = madd[nb * 8 + lc * 2];
            const float mb = madd[nb * 8 + lc * 2 + 1];
            sc[nb][0] = fmaf(sc[nb][0], SM_SCALE, ma);
            sc[nb][1] = fmaf(sc[nb][1], SM_SCALE, mb);
            sc[nb][2] = fmaf(sc[nb][2], SM_SCALE, ma);
            sc[nb][3] = fmaf(sc[nb][3], SM_SCALE, mb);
            mloc0 = fmaxf(mloc0, fmaxf(sc[nb][0], sc[nb][1]));
            mloc1 = fmaxf(mloc1, fmaxf(sc[nb][2], sc[nb][3]));
        }
        mloc0 = fmaxf(mloc0, __shfl_xor_sync(0xffffffffu, mloc0, 1));
        mloc0 = fmaxf(mloc0, __shfl_xor_sync(0xffffffffu, mloc0, 2));
        mloc1 = fmaxf(mloc1, __shfl_xor_sync(0xffffffffu, mloc1, 1));
        mloc1 = fmaxf(mloc1, __shfl_xor_sync(0xffffffffu, mloc1, 2));

        const float mn0 = fmaxf(m0, mloc0);
        const float mn1 = fmaxf(m1, mloc1);
        const float f0 = __expf(m0 - mn0);
        const float f1 = __expf(m1 - mn1);

        float s0 = 0.f, s1 = 0.f;
#pragma unroll
        for (int nb = 0; nb < 8; ++nb) {
            sc[nb][0] = __expf(sc[nb][0] - mn0);
            sc[nb][1] = __expf(sc[nb][1] - mn0);
            sc[nb][2] = __expf(sc[nb][2] - mn1);
            sc[nb][3] = __expf(sc[nb][3] - mn1);
            s0 += sc[nb][0] + sc[nb][1];
            s1 += sc[nb][2] + sc[nb][3];
        }
        s0 += __shfl_xor_sync(0xffffffffu, s0, 1);
        s0 += __shfl_xor_sync(0xffffffffu, s0, 2);
        s1 += __shfl_xor_sync(0xffffffffu, s1, 1);
        s1 += __shfl_xor_sync(0xffffffffu, s1, 2);

        l0 = l0 * f0 + s0;
        l1 = l1 * f1 + s1;
        m0 = mn0;
        m1 = mn1;

#pragma unroll
        for (int nb = 0; nb < 8; ++nb) {
            o[nb][0] *= f0; o[nb][1] *= f0;
            o[nb][2] *= f1; o[nb][3] *= f1;
        }

#pragma unroll
        for (int kj = 0; kj < 8; ++kj) {
            const int s_lo = qbase + (lc >> 1);
            const int s_hi = s_lo + 2;
            const float t0 = __shfl_sync(0xffffffffu, sc[kj][0], s_lo);
            const float t1 = __shfl_sync(0xffffffffu, sc[kj][1], s_lo);
            const float u0 = __shfl_sync(0xffffffffu, sc[kj][0], s_hi);
            const float u1 = __shfl_sync(0xffffffffu, sc[kj][1], s_hi);
            const float t2 = __shfl_sync(0xffffffffu, sc[kj][2], s_lo);
            const float t3 = __shfl_sync(0xffffffffu, sc[kj][3], s_lo);
            const float u2 = __shfl_sync(0xffffffffu, sc[kj][2], s_hi);
            const float u3 = __shfl_sync(0xffffffffu, sc[kj][3], s_hi);
            const bool odd = (lc & 1);
            uint32_t pa[4];
            pa[0] = f2tf32(odd ? t1 : t0);
            pa[1] = f2tf32(odd ? t3 : t2);
            pa[2] = f2tf32(odd ? u1 : u0);
            pa[3] = f2tf32(odd ? u3 : u2);

            const float* vr = Vs + (kj * 8 + lc) * FA_LDV + lr;
#pragma unroll
            for (int nb2 = 0; nb2 < 8; ++nb2) {
                uint32_t bf[2];
                bf[0] = __float_as_uint(vr[nb2 * 8]);
                bf[1] = __float_as_uint(vr[4 * FA_LDV + nb2 * 8]);
                mma_tf32_16x8x8(o[nb2], pa, bf);
            }
        }
        __syncthreads();
    }

    // Epilogue: normalize, round to tf32 (operand of the output GEMM), store.
    const float inv0 = 1.0f / l0;
    const float inv1 = 1.0f / l1;
    const int row0 = qt * 128 + wid * 16 + lr;
    float* Ob = O + ((size_t)(n * L) + row0) * D + h * HD;
#pragma unroll
    for (int nb = 0; nb < 8; ++nb) {
        const int col = nb * 8 + lc * 2;
        *(float2*)(Ob + col) = make_float2(
            __uint_as_float(f2tf32(o[nb][0] * inv0)),
            __uint_as_float(f2tf32(o[nb][1] * inv0)));
        *(float2*)(Ob + (size_t)8 * D + col) = make_float2(
            __uint_as_float(f2tf32(o[nb][2] * inv1)),
            __uint_as_float(f2tf32(o[nb][3] * inv1)));
    }
}

// ---------------------------------------------------------------------------
// Launch
// ---------------------------------------------------------------------------
extern "C" void kernel_launch(void* const* d_in, const int* in_sizes, int n_in,
                              void* d_out, int out_size)
{
    const float* values = (const float*)d_in[0];
    const float* key    = (const float*)d_in[1];
    const float* query  = (const float*)d_in[2];
    const int*   mask   = (const int*)d_in[3];
    const float* Wv = (const float*)d_in[4];
    const float* bv = (const float*)d_in[5];
    const float* Wk = (const float*)d_in[6];
    const float* bk = (const float*)d_in[7];
    const float* Wq = (const float*)d_in[8];
    const float* bq = (const float*)d_in[9];
    const float* Wo = (const float*)d_in[10];
    const float* bo = (const float*)d_in[11];
    float* out = (float*)d_out;

    float *Qp, *Kp, *Vp, *AOp;
    float *CVp, *CKp, *CQp, *CWvp, *CWkp, *CWqp, *CWop;
    cudaGetSymbolAddress((void**)&Qp, g_Q);
    cudaGetSymbolAddress((void**)&Kp, g_K);
    cudaGetSymbolAddress((void**)&Vp, g_V);
    cudaGetSymbolAddress((void**)&AOp, g_AO);
    cudaGetSymbolAddress((void**)&CVp, g_CV);
    cudaGetSymbolAddress((void**)&CKp, g_CK);
    cudaGetSymbolAddress((void**)&CQp, g_CQ);
    cudaGetSymbolAddress((void**)&CWvp, g_CWv);
    cudaGetSymbolAddress((void**)&CWkp, g_CWk);
    cudaGetSymbolAddress((void**)&CWqp, g_CWq);
    cudaGetSymbolAddress((void**)&CWop, g_CWo);

    cudaFuncSetAttribute(gemm_cp,
                         cudaFuncAttributeMaxDynamicSharedMemorySize,
                         G_SMEM_BYTES);
    cudaFuncSetAttribute(flash_attn_tc,
                         cudaFuncAttributeMaxDynamicSharedMemorySize,
                         FA_SMEM_BYTES);

    // One-shot tf32 rounding of GEMM operands
    cvt_all<<<16384, 256>>>(
        (const float4*)values, (const float4*)key, (const float4*)query,
        (const float4*)Wv, (const float4*)Wk, (const float4*)Wq, (const float4*)Wo,
        (float4*)CVp, (float4*)CKp, (float4*)CQp,
        (float4*)CWvp, (float4*)CWkp, (float4*)CWqp, (float4*)CWop);

    dim3 gemm_grid(D / 256, (NB * L) / 128);   // (4, 32) = 128 CTAs
    gemm_cp<<<gemm_grid, 256, G_SMEM_BYTES>>>(CQp, CWqp, bq, Qp);
    gemm_cp<<<gemm_grid, 256, G_SMEM_BYTES>>>(CKp, CWkp, bk, Kp);
    gemm_cp<<<gemm_grid, 256, G_SMEM_BYTES>>>(CVp, CWvp, bv, Vp);

    dim3 fa_grid(L / 128, H, NB);              // (16, 16, 2)
    flash_attn_tc<<<fa_grid, 256, FA_SMEM_BYTES>>>(Qp, Kp, Vp, mask, AOp);

    gemm_cp<<<gemm_grid, 256, G_SMEM_BYTES>>>(AOp, CWop, bo, out);
}